// round 9
// baseline (speedup 1.0000x reference)
#include <cuda_runtime.h>
#include <cuda_bf16.h>
#include <math.h>
#include <stdint.h>

#define BB 32
#define HH 512
#define VOCAB 50257
#define VPAD  50432          // multiple of 256
#define NB8   (VPAD/8)       // 6304 fragment columns
#define NBLK  (VPAD/256)     // 197 virtual big-gemm blocks (256 cols each)
#define NBP   208            // padded partial stride
#define NPERS 128            // persistent blocks
#define VSEG  12565          // writey segment (4 per row)

// ---------------- device scratch ----------------
__device__ float g_xcur[BB * HH];
__device__ float g_h0s[2][BB * HH];
__device__ float g_h1s[2][BB * HH];
__device__ float g_ps0[BB * 128];              // layer-0 partial row sums per block
__device__ float g_x1[BB * HH];
__device__ uint4 g_Af[2 * 32 * 2 * 32];        // [hl][ks][m][lane] A fragments
__device__ uint4 g_Bf[(long)32 * NB8 * 32];    // V1 frags {bh0,bh1,bl0,bl1} (103MB)
__device__ float g_c1p[VPAD];
__device__ float g_E[BB * VPAD];               // exp(logits1)
__device__ float g_psum[BB * NBP];
__device__ float g_pmax[BB * NBP];
__device__ int   g_pidx[BB * NBP];
__device__ float g_invS[BB];
__device__ int   g_bar;                        // monotonic grid-barrier counter
__device__ int   g_exit;

// ---------------- smem layout (float offsets) ----------------
#define OFF_A1   0        // 16512 (also big-phase frag area: 4096 uint4 = 16384 f)
#define OFF_A2   16512    // 16512
#define OFF_RED  33024    // 256
#define OFF_H    33280    // 160
#define OFF_INV  33440    // 32
#define OFF_SUM  33472    // 256
#define OFF_MAX  33728    // 256
#define OFF_IDX  33984    // 256 (int)
#define OFF_W    34240    // 5 * 2064 = 10320
#define SMEM_F   44560
#define SMEM_BYTES (SMEM_F * 4)

// ---------------- helpers ----------------
__device__ __forceinline__ uint32_t pk_bf2(float a, float b) {
    uint32_t ua = (uint32_t)__bfloat16_as_ushort(__float2bfloat16_rn(a));
    uint32_t ub = (uint32_t)__bfloat16_as_ushort(__float2bfloat16_rn(b));
    return ua | (ub << 16);
}
__device__ __forceinline__ float bf_hi(float v) {
    return __bfloat162float(__float2bfloat16_rn(v));
}
__device__ __forceinline__ void mma_bf16(float* d, const uint4& a, uint32_t b0, uint32_t b1) {
    asm volatile(
        "mma.sync.aligned.m16n8k16.row.col.f32.bf16.bf16.f32 "
        "{%0,%1,%2,%3},{%4,%5,%6,%7},{%8,%9},{%0,%1,%2,%3};\n"
        : "+f"(d[0]), "+f"(d[1]), "+f"(d[2]), "+f"(d[3])
        : "r"(a.x), "r"(a.y), "r"(a.z), "r"(a.w), "r"(b0), "r"(b1));
}
// grid barrier: target = absolute count (gen * NPERS)
__device__ __forceinline__ void gbar(int target) {
    __syncthreads();
    if (threadIdx.x == 0) {
        __threadfence();
        atomicAdd(&g_bar, 1);
        while (*((volatile int*)&g_bar) < target) { }
        __threadfence();
    }
    __syncthreads();
}
// stage a 32x512 fp32 matrix into smem with 516-stride rows
__device__ __forceinline__ void stageA(const float* __restrict__ A, float* sA, int tid) {
    const float4* g = (const float4*)A;
    #pragma unroll
    for (int i = 0; i < 16; i++) {
        int q = tid + i * 256;
        ((float4*)(sA + (q >> 7) * 516))[q & 127] = g[q];
    }
}
// one K-half dot product against a staged weight column
__device__ __forceinline__ float dotp(const float* sA, const float* sWm,
                                      int half, int r, int jl) {
    const float4* a = (const float4*)(sA + r * 516) + half * 64;
    const float4* w = (const float4*)(sWm + jl * 516) + half * 64;
    float ac0 = 0.f, ac1 = 0.f, ac2 = 0.f, ac3 = 0.f;
    #pragma unroll
    for (int k = 0; k < 64; k += 4) {
        float4 x0 = a[k],     y0 = w[k];
        float4 x1 = a[k + 1], y1 = w[k + 1];
        float4 x2 = a[k + 2], y2 = w[k + 2];
        float4 x3 = a[k + 3], y3 = w[k + 3];
        ac0 = fmaf(x0.x, y0.x, ac0); ac0 = fmaf(x0.y, y0.y, ac0);
        ac0 = fmaf(x0.z, y0.z, ac0); ac0 = fmaf(x0.w, y0.w, ac0);
        ac1 = fmaf(x1.x, y1.x, ac1); ac1 = fmaf(x1.y, y1.y, ac1);
        ac1 = fmaf(x1.z, y1.z, ac1); ac1 = fmaf(x1.w, y1.w, ac1);
        ac2 = fmaf(x2.x, y2.x, ac2); ac2 = fmaf(x2.y, y2.y, ac2);
        ac2 = fmaf(x2.z, y2.z, ac2); ac2 = fmaf(x2.w, y2.w, ac2);
        ac3 = fmaf(x3.x, y3.x, ac3); ac3 = fmaf(x3.y, y3.y, ac3);
        ac3 = fmaf(x3.z, y3.z, ac3); ac3 = fmaf(x3.w, y3.w, ac3);
    }
    return (ac0 + ac1) + (ac2 + ac3);
}

// ---------------- one-time kernels ----------------
__global__ void k_init(const int* __restrict__ x, const float* __restrict__ h_prev,
                       const float* __restrict__ emb) {
    int b = blockIdx.x, j = threadIdx.x;
    g_xcur[b * HH + j]   = emb[(long)x[b] * HH + j];
    g_h0s[0][b * HH + j] = h_prev[b * HH + j];
    g_h1s[0][b * HH + j] = h_prev[b * HH + j];
}

__global__ void k_pack_c1(const float* __restrict__ c1) {
    int i = blockIdx.x * blockDim.x + threadIdx.x;
    if (i < VPAD) g_c1p[i] = (i < VOCAB) ? c1[i] : -1e30f;
}

__global__ void k_pack_b(const float* __restrict__ V1) {
    __shared__ float sv[16][257];
    int bx = blockIdx.x, ks = blockIdx.y, tid = threadIdx.x;
    int cbase = bx * 256;
    #pragma unroll
    for (int r = 0; r < 16; r++) {
        int col = cbase + tid;
        int k = ks * 16 + r;
        sv[r][tid] = (col < VOCAB) ? V1[(long)k * VOCAB + col] : 0.0f;
    }
    __syncthreads();
    for (int e = tid; e < 1024; e += 256) {
        int lane = e & 31, n8l = e >> 5;
        int colL = n8l * 8 + (lane >> 2);
        int rr = (lane & 3) * 2;
        float v0 = sv[rr][colL],     v1 = sv[rr + 1][colL];
        float v8 = sv[rr + 8][colL], v9 = sv[rr + 9][colL];
        float h0 = bf_hi(v0), h1 = bf_hi(v1), h8 = bf_hi(v8), h9 = bf_hi(v9);
        uint4 o;
        o.x = pk_bf2(h0, h1);
        o.y = pk_bf2(h8, h9);
        o.z = pk_bf2(v0 - h0, v1 - h1);
        o.w = pk_bf2(v8 - h8, v9 - h9);
        g_Bf[((long)ks * NB8 + bx * 32 + n8l) * 32 + lane] = o;
    }
}

// ---------------- THE persistent kernel: all 64 steps ----------------
__global__ void __launch_bounds__(256) k_steps(
        const float* __restrict__ U0, const float* __restrict__ W0,
        const float* __restrict__ b0, const float* __restrict__ V0,
        const float* __restrict__ c0, const float* __restrict__ U1,
        const float* __restrict__ W1, const float* __restrict__ b1,
        const float* __restrict__ emb,
        float* __restrict__ out_h, float* __restrict__ out_y, int T) {
    extern __shared__ float sm[];
    float* sA1  = sm + OFF_A1;
    float* sA2  = sm + OFF_A2;
    float* sRed = sm + OFF_RED;
    float* sH   = sm + OFF_H;
    float* sInv = sm + OFF_INV;
    float* sSum = sm + OFF_SUM;
    float* sMax = sm + OFF_MAX;
    int*   sIdx = (int*)(sm + OFF_IDX);
    float* sW   = sm + OFF_W;
    uint4* sFrag = (uint4*)sm;

    int tid = threadIdx.x, bx = blockIdx.x;
    int jb = bx * 4;
    int half = tid >> 7, sub = tid & 127;
    int jl = sub & 3, r = sub >> 2;
    int w = tid >> 5, lane = tid & 31;

    // stage this block's weight columns ONCE for all steps
    {
        const float* mats[5] = {U0, W0, V0, U1, W1};
        #pragma unroll
        for (int m = 0; m < 5; m++) {
            const float* src = mats[m];
            float* dst = sW + m * 2064;
            #pragma unroll
            for (int i = 0; i < 8; i++) {
                int q = tid + i * 256;
                int kk = q >> 2, jj = q & 3;
                dst[jj * 516 + kk] = src[kk * 512 + jb + jj];
            }
        }
    }
    __syncthreads();

    int gen = 0;
    for (int t = 0; t < T; t++) {
        int cur = t & 1, nxt = cur ^ 1;

        // ---- P0: h0n = tanh(x@U0 + h0@W0 + b0) ----
        stageA(g_xcur, sA1, tid);
        stageA(g_h0s[cur], sA2, tid);
        __syncthreads();
        {
            float p = dotp(sA1, sW + 0 * 2064, half, r, jl)
                    + dotp(sA2, sW + 1 * 2064, half, r, jl);
            sRed[half * 128 + sub] = p;
        }
        __syncthreads();
        if (tid < 128) {
            float o = tanhf(sRed[tid] + sRed[128 + tid] + b0[jb + jl]);
            g_h0s[nxt][r * 512 + jb + jl] = o;
        }
        gbar(++gen * NPERS);

        // ---- P1: e0 = exp(h0n@V0 + c0), block partial sums ----
        stageA(g_h0s[nxt], sA1, tid);
        __syncthreads();
        {
            float p = dotp(sA1, sW + 2 * 2064, half, r, jl);
            sRed[half * 128 + sub] = p;
        }
        __syncthreads();
        float ereg = 0.f;
        if (tid < 128) {
            float o = sRed[tid] + sRed[128 + tid] + c0[jb + jl];
            ereg = __expf(o);                       // |logits0| small: shift-free safe
            float v = ereg;
            v += __shfl_down_sync(0xffffffffu, v, 2);
            v += __shfl_down_sync(0xffffffffu, v, 1);
            if ((tid & 3) == 0) g_ps0[r * 128 + bx] = v;
        }
        gbar(++gen * NPERS);

        // ---- P2: x1 = tanh(e0 / S) ----
        if (tid < 128) {
            int row = tid >> 2, q = tid & 3;
            float s = 0.f;
            #pragma unroll 8
            for (int i = 0; i < 32; i++) s += g_ps0[row * 128 + q * 32 + i];
            s += __shfl_xor_sync(0xffffffffu, s, 1);
            s += __shfl_xor_sync(0xffffffffu, s, 2);
            if (q == 0) sInv[row] = 1.0f / s;
        }
        __syncthreads();
        if (tid < 128) g_x1[r * 512 + jb + jl] = tanhf(ereg * sInv[r]);
        gbar(++gen * NPERS);

        // ---- P3: h1n = tanh(x1@U1 + h1@W1 + b1) + out_h + frag pack ----
        stageA(g_x1, sA1, tid);
        stageA(g_h1s[cur], sA2, tid);
        __syncthreads();
        {
            float p = dotp(sA1, sW + 3 * 2064, half, r, jl)
                    + dotp(sA2, sW + 4 * 2064, half, r, jl);
            sRed[half * 128 + sub] = p;
        }
        __syncthreads();
        if (tid < 128) {
            float o = tanhf(sRed[tid] + sRed[128 + tid] + b1[jb + jl]);
            g_h1s[nxt][r * 512 + jb + jl] = o;
            out_h[((long)r * T + t) * 512 + jb + jl] = o;
            sH[r * 5 + jl] = o;
        }
        __syncthreads();
        if (tid < 128) {
            int hl = tid >> 6, rem = tid & 63;
            int ps = rem & 1, rr = rem >> 1;
            int c0i = jb + ps * 2;
            float v0 = sH[rr * 5 + ps * 2], v1 = sH[rr * 5 + ps * 2 + 1];
            float h0f = bf_hi(v0), h1f = bf_hi(v1);
            uint32_t pk = hl ? pk_bf2(v0 - h0f, v1 - h1f) : pk_bf2(h0f, h1f);
            int ks2 = c0i >> 4, kk = c0i & 15;
            int hcol = (kk >> 3) & 1, g2 = (kk >> 1) & 3;
            int lane2 = (rr & 7) * 4 + g2;
            int reg = hcol * 2 + ((rr >> 3) & 1);
            int mtile = rr >> 4;
            ((uint32_t*)g_Af)[(((hl * 32 + ks2) * 2 + mtile) * 32 + lane2) * 4 + reg] = pk;
        }
        gbar(++gen * NPERS);

        // ---- BIG: logits1 -> exp + per-vbx partials ----
        #pragma unroll
        for (int i = 0; i < 16; i++) sFrag[tid + i * 256] = g_Af[tid + i * 256];
        __syncthreads();
        for (int vbx = bx; vbx < NBLK; vbx += NPERS) {
            int n8base = vbx * 32 + w * 4;
            float acc[2][4][4];
            #pragma unroll
            for (int m = 0; m < 2; m++)
                #pragma unroll
                for (int n = 0; n < 4; n++)
                    #pragma unroll
                    for (int rr = 0; rr < 4; rr++) acc[m][n][rr] = 0.f;

            #pragma unroll 2
            for (int ks = 0; ks < 32; ks++) {
                uint4 ah0 = sFrag[(ks * 2 + 0) * 32 + lane];
                uint4 ah1 = sFrag[(ks * 2 + 1) * 32 + lane];
                uint4 al0 = sFrag[((32 + ks) * 2 + 0) * 32 + lane];
                uint4 al1 = sFrag[((32 + ks) * 2 + 1) * 32 + lane];
                uint4 bv[4];
                #pragma unroll
                for (int n = 0; n < 4; n++)
                    bv[n] = g_Bf[((long)ks * NB8 + n8base + n) * 32 + lane];
                #pragma unroll
                for (int n = 0; n < 4; n++) {
                    mma_bf16(acc[0][n], ah0, bv[n].x, bv[n].y);
                    mma_bf16(acc[1][n], ah1, bv[n].x, bv[n].y);
                    mma_bf16(acc[0][n], al0, bv[n].x, bv[n].y);
                    mma_bf16(acc[1][n], al1, bv[n].x, bv[n].y);
                    mma_bf16(acc[0][n], ah0, bv[n].z, bv[n].w);
                    mma_bf16(acc[1][n], ah1, bv[n].z, bv[n].w);
                }
            }

            int colw = vbx * 256 + w * 32;
            float rsum[4] = {0.f, 0.f, 0.f, 0.f};
            float rmax[4] = {-3e38f, -3e38f, -3e38f, -3e38f};
            int   ridx[4] = {0, 0, 0, 0};
            #pragma unroll
            for (int m = 0; m < 2; m++) {
                #pragma unroll
                for (int n = 0; n < 4; n++) {
                    int c0c = colw + n * 8 + ((lane & 3) << 1);
                    float bias0 = g_c1p[c0c], bias1 = g_c1p[c0c + 1];
                    {
                        float l0 = acc[m][n][0] + bias0, l1 = acc[m][n][1] + bias1;
                        float e0 = __expf(l0), e1 = __expf(l1);
                        int row = m * 16 + (lane >> 2);
                        *(float2*)&g_E[(long)row * VPAD + c0c] = make_float2(e0, e1);
                        int slot = m * 2;
                        rsum[slot] += e0 + e1;
                        if (l0 > rmax[slot] || (l0 == rmax[slot] && c0c < ridx[slot])) { rmax[slot] = l0; ridx[slot] = c0c; }
                        if (l1 > rmax[slot] || (l1 == rmax[slot] && c0c + 1 < ridx[slot])) { rmax[slot] = l1; ridx[slot] = c0c + 1; }
                    }
                    {
                        float l0 = acc[m][n][2] + bias0, l1 = acc[m][n][3] + bias1;
                        float e0 = __expf(l0), e1 = __expf(l1);
                        int row = m * 16 + (lane >> 2) + 8;
                        *(float2*)&g_E[(long)row * VPAD + c0c] = make_float2(e0, e1);
                        int slot = m * 2 + 1;
                        rsum[slot] += e0 + e1;
                        if (l0 > rmax[slot] || (l0 == rmax[slot] && c0c < ridx[slot])) { rmax[slot] = l0; ridx[slot] = c0c; }
                        if (l1 > rmax[slot] || (l1 == rmax[slot] && c0c + 1 < ridx[slot])) { rmax[slot] = l1; ridx[slot] = c0c + 1; }
                    }
                }
            }
            #pragma unroll
            for (int off = 1; off <= 2; off <<= 1) {
                #pragma unroll
                for (int slot = 0; slot < 4; slot++) {
                    rsum[slot] += __shfl_xor_sync(0xffffffffu, rsum[slot], off);
                    float v = __shfl_xor_sync(0xffffffffu, rmax[slot], off);
                    int   i = __shfl_xor_sync(0xffffffffu, ridx[slot], off);
                    if (v > rmax[slot] || (v == rmax[slot] && i < ridx[slot])) { rmax[slot] = v; ridx[slot] = i; }
                }
            }
            if ((lane & 3) == 0) {
                #pragma unroll
                for (int slot = 0; slot < 4; slot++) {
                    int row = (slot >> 1) * 16 + (lane >> 2) + (slot & 1) * 8;
                    sSum[w * 32 + row] = rsum[slot];
                    sMax[w * 32 + row] = rmax[slot];
                    sIdx[w * 32 + row] = ridx[slot];
                }
            }
            __syncthreads();
            if (tid < 32) {
                int row = tid;
                float ps = 0.f, pv = -3e38f; int pi = 0;
                #pragma unroll
                for (int ww = 0; ww < 8; ww++) {
                    ps += sSum[ww * 32 + row];
                    float v = sMax[ww * 32 + row]; int i = sIdx[ww * 32 + row];
                    if (v > pv || (v == pv && i < pi)) { pv = v; pi = i; }
                }
                g_psum[row * NBP + vbx] = ps;
                g_pmax[row * NBP + vbx] = pv;
                g_pidx[row * NBP + vbx] = pi;
            }
            __syncthreads();
        }
        gbar(++gen * NPERS);

        // ---- COMB: invS + argmax + feedback embed (blocks 0..31) ----
        if (bx < 32) {
            int row = bx;
            float s = 0.f, mv = -3e38f; int mi = 0;
            if (tid < NBLK) {
                s = g_psum[row * NBP + tid];
                mv = g_pmax[row * NBP + tid];
                mi = g_pidx[row * NBP + tid];
            }
            sRed[tid] = s; sMax[tid] = mv; sIdx[tid] = mi;
            __syncthreads();
            for (int st = 128; st > 0; st >>= 1) {
                if (tid < st) {
                    sRed[tid] += sRed[tid + st];
                    float v = sMax[tid + st]; int i = sIdx[tid + st];
                    if (v > sMax[tid] || (v == sMax[tid] && i < sIdx[tid])) { sMax[tid] = v; sIdx[tid] = i; }
                }
                __syncthreads();
            }
            if (tid == 0) g_invS[row] = 1.0f / sRed[0];
            int am = sIdx[0];
            g_xcur[row * 512 + tid]       = emb[(long)am * 512 + tid];
            g_xcur[row * 512 + tid + 256] = emb[(long)am * 512 + tid + 256];
        }
        gbar(++gen * NPERS);

        // ---- WRITEY (no trailing barrier needed) ----
        {
            int b = bx >> 2, seg = bx & 3;
            float inv = g_invS[b];
            const float* erow = g_E + (long)b * VPAD;
            float* yrow = out_y + ((long)b * T + t) * VOCAB;
            int end = min((seg + 1) * VSEG, VOCAB);
            for (int j = seg * VSEG + tid; j < end; j += 256)
                yrow[j] = erow[j] * inv;
        }
    }

    // reset barrier counters for the next launch (last-arriving block)
    __syncthreads();
    if (tid == 0) {
        __threadfence();
        int v = atomicAdd(&g_exit, 1);
        if (v == (int)gridDim.x - 1) {
            g_bar = 0;
            g_exit = 0;
            __threadfence();
        }
    }
}

// ---------------- host launcher ----------------
extern "C" void kernel_launch(void* const* d_in, const int* in_sizes, int n_in,
                              void* d_out, int out_size) {
    const int*   x      = (const int*)d_in[0];
    const float* h_prev = (const float*)d_in[3];
    const float* emb    = (const float*)d_in[4];
    const float* U0     = (const float*)d_in[5];
    const float* W0     = (const float*)d_in[6];
    const float* b0     = (const float*)d_in[7];
    const float* V0     = (const float*)d_in[8];
    const float* c0     = (const float*)d_in[9];
    const float* U1     = (const float*)d_in[10];
    const float* W1     = (const float*)d_in[11];
    const float* b1     = (const float*)d_in[12];
    const float* V1     = (const float*)d_in[13];
    const float* c1     = (const float*)d_in[14];

    float* out = (float*)d_out;
    int T = out_size / (BB * (HH + VOCAB));
    float* out_h = out;
    float* out_y = out + (long)BB * T * HH;

    static bool attr_set = false;
    if (!attr_set) {
        cudaFuncSetAttribute(k_steps, cudaFuncAttributeMaxDynamicSharedMemorySize, SMEM_BYTES);
        attr_set = true;
    }

    k_init<<<BB, 512>>>(x, h_prev, emb);
    k_pack_c1<<<(VPAD + 255) / 256, 256>>>(c1);
    k_pack_b<<<dim3(197, 32), 256>>>(V1);
    k_steps<<<NPERS, 256, SMEM_BYTES>>>(U0, W0, b0, V0, c0, U1, W1, b1,
                                        emb, out_h, out_y, T);
}

// round 10
// speedup vs baseline: 1.1293x; 1.1293x over previous
#include <cuda_runtime.h>
#include <cuda_bf16.h>
#include <math.h>
#include <stdint.h>

#define BB 32
#define HH 512
#define VOCAB 50257
#define VPAD  50688          // multiple of 512 (99 * 512)
#define NB8   (VPAD/8)       // 6336 fragment columns
#define NBLK  (VPAD/512)     // 99 big-gemm blocks (512 cols each)
#define NBP   104            // padded partial stride
#define NF4   12565          // float4 groups per vocab row (last partial)

// ---------------- device scratch ----------------
__device__ float g_xcur[BB * HH];
__device__ float g_h0s[2][BB * HH];
__device__ float g_h1s[2][BB * HH];
__device__ float g_e0[BB * HH];                // exp(logits0)
__device__ float g_ps0[BB * 128];              // layer-0 partial row sums per block
__device__ uint4 g_Af[2 * 32 * 2 * 32];        // [hl][ks][m][lane] A fragments for k_big
__device__ uint4 g_Bf[(long)32 * NB8 * 32];    // [ks][n8][lane] -> {bh0,bh1,bl0,bl1}
__device__ float g_c1p[VPAD];
__device__ float g_E[BB * VPAD];               // exp(logits1)
__device__ float g_psum[BB * NBP];
__device__ float g_pmax[BB * NBP];
__device__ int   g_pidx[BB * NBP];
__device__ float g_invS[BB];

// ---------------- helpers ----------------
__device__ __forceinline__ uint32_t pk_bf2(float a, float b) {
    uint32_t ua = (uint32_t)__bfloat16_as_ushort(__float2bfloat16_rn(a));
    uint32_t ub = (uint32_t)__bfloat16_as_ushort(__float2bfloat16_rn(b));
    return ua | (ub << 16);
}
__device__ __forceinline__ float bf_hi(float v) {
    return __bfloat162float(__float2bfloat16_rn(v));
}
__device__ __forceinline__ void mma_bf16(float* d, const uint4& a, uint32_t b0, uint32_t b1) {
    asm volatile(
        "mma.sync.aligned.m16n8k16.row.col.f32.bf16.bf16.f32 "
        "{%0,%1,%2,%3},{%4,%5,%6,%7},{%8,%9},{%0,%1,%2,%3};\n"
        : "+f"(d[0]), "+f"(d[1]), "+f"(d[2]), "+f"(d[3])
        : "r"(a.x), "r"(a.y), "r"(a.z), "r"(a.w), "r"(b0), "r"(b1));
}

// ---------------- one-time kernels ----------------
__global__ void k_init(const int* __restrict__ x, const float* __restrict__ h_prev,
                       const float* __restrict__ emb) {
    int b = blockIdx.x, j = threadIdx.x;
    g_xcur[b * HH + j]   = emb[(long)x[b] * HH + j];
    g_h0s[0][b * HH + j] = h_prev[b * HH + j];
    g_h1s[0][b * HH + j] = h_prev[b * HH + j];
}

__global__ void k_pack_c1(const float* __restrict__ c1) {
    int i = blockIdx.x * blockDim.x + threadIdx.x;
    if (i < VPAD) g_c1p[i] = (i < VOCAB) ? c1[i] : -1e30f;
}

__global__ void k_pack_b(const float* __restrict__ V1) {
    __shared__ float sv[16][257];
    int bx = blockIdx.x, ks = blockIdx.y, tid = threadIdx.x;
    int cbase = bx * 256;
    #pragma unroll
    for (int r = 0; r < 16; r++) {
        int col = cbase + tid;
        int k = ks * 16 + r;
        sv[r][tid] = (col < VOCAB) ? V1[(long)k * VOCAB + col] : 0.0f;
    }
    __syncthreads();
    for (int e = tid; e < 1024; e += 256) {
        int lane = e & 31, n8l = e >> 5;
        int colL = n8l * 8 + (lane >> 2);
        int rr = (lane & 3) * 2;
        float v0 = sv[rr][colL],     v1 = sv[rr + 1][colL];
        float v8 = sv[rr + 8][colL], v9 = sv[rr + 9][colL];
        float h0 = bf_hi(v0), h1 = bf_hi(v1), h8 = bf_hi(v8), h9 = bf_hi(v9);
        uint4 o;
        o.x = pk_bf2(h0, h1);
        o.y = pk_bf2(h8, h9);
        o.z = pk_bf2(v0 - h0, v1 - h1);
        o.w = pk_bf2(v8 - h8, v9 - h9);
        g_Bf[((long)ks * NB8 + bx * 32 + n8l) * 32 + lane] = o;
    }
}

// ---------------- small GEMM: full staging, 256 threads, 2-way split-K ----------------
// MODE 0: cell0  h0n = tanh(x@U0 + h0@W0 + b0)      + writes y(t-1) first half
// MODE 1: head0  e0 = exp(h0n@V0 + c0), partials    + writes y(t-1) second half
// MODE 2: cell1  inv from ps0; x1 = tanh(e0*inv) staged inline;
//                h1n = tanh(x1@U1 + h1@W1 + b1) + out_h + frag pack
template<int MODE>
__global__ void __launch_bounds__(256) k_cellx(
        const float* __restrict__ A1, const float* __restrict__ A2,
        const float* __restrict__ W1, const float* __restrict__ W2,
        const float* __restrict__ bias, float* __restrict__ outp,
        float* __restrict__ out_h, float* __restrict__ out_y,
        int t, int tprev, int T) {
    constexpr bool DUAL = (MODE != 1);
    extern __shared__ float sm[];
    float* sA1 = sm;                                   // 32 x 516
    float* sA2 = DUAL ? (sm + 16512) : nullptr;        // 32 x 516
    float* sW1 = sm + (DUAL ? 33024 : 16512);          // 4 x 516
    float* sW2 = DUAL ? (sW1 + 2064) : nullptr;        // 4 x 516
    float* sRed = sW1 + (DUAL ? 4128 : 2064);          // 256
    float* sH  = sRed + 256;                           // 32 x 5 (MODE 2)
    float* sInv = sH + 160;                            // 32 (MODE 2)

    int tid = threadIdx.x;
    int bx = blockIdx.x;
    int jb = bx * 4;
    int half = tid >> 7;
    int sub  = tid & 127;
    int jl = sub & 3, r = sub >> 2;

    // ---- folded y-write for step t-1 (MODE 0: first half, MODE 1: second half) ----
    if (MODE != 2 && tprev >= 0) {
        constexpr int LO   = (MODE == 0) ? 0 : 6283;
        constexpr int SPAN = (MODE == 0) ? 6283 : (NF4 - 6283);
        int total = 32 * SPAN;
        for (int idx = bx * 256 + tid; idx < total; idx += 128 * 256) {
            int row = idx / SPAN;
            int q = LO + (idx - row * SPAN);
            float4 v = *(const float4*)(g_E + (long)row * VPAD + q * 4);
            float inv = g_invS[row];
            float* dst = out_y + ((long)row * T + tprev) * VOCAB;
            int c = q * 4;
            if (c + 3 < VOCAB) {
                dst[c] = v.x * inv; dst[c + 1] = v.y * inv;
                dst[c + 2] = v.z * inv; dst[c + 3] = v.w * inv;
            } else {
                if (c < VOCAB) dst[c] = v.x * inv;
                if (c + 1 < VOCAB) dst[c + 1] = v.y * inv;
                if (c + 2 < VOCAB) dst[c + 2] = v.z * inv;
            }
        }
    }

    // ---- MODE 2: compute per-row inv from layer-0 partials ----
    if (MODE == 2) {
        if (tid < 128) {
            int row = tid >> 2, qq = tid & 3;
            float s = 0.f;
            #pragma unroll 8
            for (int i = 0; i < 32; i++) s += g_ps0[row * 128 + qq * 32 + i];
            s += __shfl_xor_sync(0xffffffffu, s, 1);
            s += __shfl_xor_sync(0xffffffffu, s, 2);
            if (qq == 0) sInv[row] = 1.0f / s;
        }
        __syncthreads();
    }

    // ---- stage A matrices ----
    if (MODE == 2) {
        // A1 = x1 = tanh(e0 * inv), computed inline from g_e0
        #pragma unroll
        for (int i = 0; i < 16; i++) {
            int q = tid + i * 256;
            int rr = q >> 7, cc = q & 127;
            float4 e = ((const float4*)g_e0)[q];
            float iv = sInv[rr];
            float4 xv;
            xv.x = tanhf(e.x * iv); xv.y = tanhf(e.y * iv);
            xv.z = tanhf(e.z * iv); xv.w = tanhf(e.w * iv);
            ((float4*)(sA1 + rr * 516))[cc] = xv;
        }
    } else {
        const float4* gA1 = (const float4*)A1;
        #pragma unroll
        for (int i = 0; i < 16; i++) {
            int q = tid + i * 256;
            ((float4*)(sA1 + (q >> 7) * 516))[q & 127] = gA1[q];
        }
    }
    if (DUAL) {
        const float4* gA2 = (const float4*)A2;
        #pragma unroll
        for (int i = 0; i < 16; i++) {
            int q = tid + i * 256;
            ((float4*)(sA2 + (q >> 7) * 516))[q & 127] = gA2[q];
        }
    }
    #pragma unroll
    for (int i = 0; i < 8; i++) {
        int q = tid + i * 256;
        int kk = q >> 2, jj = q & 3;
        sW1[jj * 516 + kk] = W1[kk * 512 + jb + jj];
        if (DUAL) sW2[jj * 516 + kk] = W2[kk * 512 + jb + jj];
    }
    __syncthreads();

    // ---- compute: K half of 256 per thread, 4 accumulators ----
    float ac0 = 0.f, ac1 = 0.f, ac2 = 0.f, ac3 = 0.f;
    {
        const float4* a1 = (const float4*)(sA1 + r * 516) + half * 64;
        const float4* w1 = (const float4*)(sW1 + jl * 516) + half * 64;
        #pragma unroll
        for (int k = 0; k < 64; k += 4) {
            float4 x0 = a1[k],     y0 = w1[k];
            float4 x1v = a1[k + 1], y1 = w1[k + 1];
            float4 x2 = a1[k + 2], y2 = w1[k + 2];
            float4 x3 = a1[k + 3], y3 = w1[k + 3];
            ac0 = fmaf(x0.x, y0.x, ac0); ac0 = fmaf(x0.y, y0.y, ac0);
            ac0 = fmaf(x0.z, y0.z, ac0); ac0 = fmaf(x0.w, y0.w, ac0);
            ac1 = fmaf(x1v.x, y1.x, ac1); ac1 = fmaf(x1v.y, y1.y, ac1);
            ac1 = fmaf(x1v.z, y1.z, ac1); ac1 = fmaf(x1v.w, y1.w, ac1);
            ac2 = fmaf(x2.x, y2.x, ac2); ac2 = fmaf(x2.y, y2.y, ac2);
            ac2 = fmaf(x2.z, y2.z, ac2); ac2 = fmaf(x2.w, y2.w, ac2);
            ac3 = fmaf(x3.x, y3.x, ac3); ac3 = fmaf(x3.y, y3.y, ac3);
            ac3 = fmaf(x3.z, y3.z, ac3); ac3 = fmaf(x3.w, y3.w, ac3);
        }
    }
    if (DUAL) {
        const float4* a2 = (const float4*)(sA2 + r * 516) + half * 64;
        const float4* w2 = (const float4*)(sW2 + jl * 516) + half * 64;
        #pragma unroll
        for (int k = 0; k < 64; k += 4) {
            float4 x0 = a2[k],     y0 = w2[k];
            float4 x1v = a2[k + 1], y1 = w2[k + 1];
            float4 x2 = a2[k + 2], y2 = w2[k + 2];
            float4 x3 = a2[k + 3], y3 = w2[k + 3];
            ac0 = fmaf(x0.x, y0.x, ac0); ac0 = fmaf(x0.y, y0.y, ac0);
            ac0 = fmaf(x0.z, y0.z, ac0); ac0 = fmaf(x0.w, y0.w, ac0);
            ac1 = fmaf(x1v.x, y1.x, ac1); ac1 = fmaf(x1v.y, y1.y, ac1);
            ac1 = fmaf(x1v.z, y1.z, ac1); ac1 = fmaf(x1v.w, y1.w, ac1);
            ac2 = fmaf(x2.x, y2.x, ac2); ac2 = fmaf(x2.y, y2.y, ac2);
            ac2 = fmaf(x2.z, y2.z, ac2); ac2 = fmaf(x2.w, y2.w, ac2);
            ac3 = fmaf(x3.x, y3.x, ac3); ac3 = fmaf(x3.y, y3.y, ac3);
            ac3 = fmaf(x3.z, y3.z, ac3); ac3 = fmaf(x3.w, y3.w, ac3);
        }
    }
    sRed[half * 128 + sub] = (ac0 + ac1) + (ac2 + ac3);
    __syncthreads();

    // ---- epilogue ----
    if (tid < 128) {
        float o = sRed[tid] + sRed[128 + tid] + bias[jb + jl];
        if (MODE == 0) {
            o = tanhf(o);
            outp[r * 512 + jb + jl] = o;
        } else if (MODE == 1) {
            float e = __expf(o);                 // |logits0| small: shift-free safe
            g_e0[r * 512 + jb + jl] = e;
            float v = e;
            v += __shfl_down_sync(0xffffffffu, v, 2);
            v += __shfl_down_sync(0xffffffffu, v, 1);
            if ((tid & 3) == 0) g_ps0[r * 128 + bx] = v;
        } else {
            o = tanhf(o);
            outp[r * 512 + jb + jl] = o;
            out_h[((long)r * T + t) * 512 + jb + jl] = o;
            sH[r * 5 + jl] = o;
        }
    }
    if (MODE == 2) {
        __syncthreads();
        if (tid < 128) {
            int hl = tid >> 6, rem = tid & 63;
            int ps = rem & 1, rr = rem >> 1;
            int c0i = jb + ps * 2;
            float v0 = sH[rr * 5 + ps * 2], v1 = sH[rr * 5 + ps * 2 + 1];
            float h0f = bf_hi(v0), h1f = bf_hi(v1);
            uint32_t pk = hl ? pk_bf2(v0 - h0f, v1 - h1f) : pk_bf2(h0f, h1f);
            int ks = c0i >> 4, kk = c0i & 15;
            int hcol = (kk >> 3) & 1, g = (kk >> 1) & 3;
            int lane = (rr & 7) * 4 + g;
            int reg = hcol * 2 + ((rr >> 3) & 1);
            int mtile = rr >> 4;
            ((uint32_t*)g_Af)[(((hl * 32 + ks) * 2 + mtile) * 32 + lane) * 4 + reg] = pk;
        }
    }
}

// ---------------- big GEMM: 512 threads/block, 512 cols/block ----------------
__global__ void __launch_bounds__(512) k_big() {
    int tid = threadIdx.x, w = tid >> 5, lane = tid & 31;
    int bx = blockIdx.x;
    int n8base = bx * 64 + w * 4;          // 16 warps x 4 n8 = 64 n8 = 512 cols
    float acc[2][4][4];
    #pragma unroll
    for (int m = 0; m < 2; m++)
        #pragma unroll
        for (int n = 0; n < 4; n++)
            #pragma unroll
            for (int rr = 0; rr < 4; rr++) acc[m][n][rr] = 0.f;

    #pragma unroll 2
    for (int ks = 0; ks < 32; ks++) {
        uint4 ah0 = g_Af[(ks * 2 + 0) * 32 + lane];
        uint4 ah1 = g_Af[(ks * 2 + 1) * 32 + lane];
        uint4 al0 = g_Af[((32 + ks) * 2 + 0) * 32 + lane];
        uint4 al1 = g_Af[((32 + ks) * 2 + 1) * 32 + lane];
        uint4 bv[4];
        #pragma unroll
        for (int n = 0; n < 4; n++)
            bv[n] = g_Bf[((long)ks * NB8 + n8base + n) * 32 + lane];
        #pragma unroll
        for (int n = 0; n < 4; n++) {
            mma_bf16(acc[0][n], ah0, bv[n].x, bv[n].y);
            mma_bf16(acc[1][n], ah1, bv[n].x, bv[n].y);
            mma_bf16(acc[0][n], al0, bv[n].x, bv[n].y);
            mma_bf16(acc[1][n], al1, bv[n].x, bv[n].y);
            mma_bf16(acc[0][n], ah0, bv[n].z, bv[n].w);
            mma_bf16(acc[1][n], ah1, bv[n].z, bv[n].w);
        }
    }

    __shared__ float s_sum[16][32];
    __shared__ float s_max[16][32];
    __shared__ int   s_idx[16][32];
    int colw = bx * 512 + w * 32;
    float rsum[4] = {0.f, 0.f, 0.f, 0.f};
    float rmax[4] = {-3e38f, -3e38f, -3e38f, -3e38f};
    int   ridx[4] = {0, 0, 0, 0};

    #pragma unroll
    for (int m = 0; m < 2; m++) {
        #pragma unroll
        for (int n = 0; n < 4; n++) {
            int c0 = colw + n * 8 + ((lane & 3) << 1);
            float bias0 = g_c1p[c0], bias1 = g_c1p[c0 + 1];
            {
                float l0 = acc[m][n][0] + bias0, l1 = acc[m][n][1] + bias1;
                float e0 = __expf(l0), e1 = __expf(l1);
                int row = m * 16 + (lane >> 2);
                *(float2*)&g_E[(long)row * VPAD + c0] = make_float2(e0, e1);
                int slot = m * 2;
                rsum[slot] += e0 + e1;
                if (l0 > rmax[slot] || (l0 == rmax[slot] && c0 < ridx[slot])) { rmax[slot] = l0; ridx[slot] = c0; }
                if (l1 > rmax[slot] || (l1 == rmax[slot] && c0 + 1 < ridx[slot])) { rmax[slot] = l1; ridx[slot] = c0 + 1; }
            }
            {
                float l0 = acc[m][n][2] + bias0, l1 = acc[m][n][3] + bias1;
                float e0 = __expf(l0), e1 = __expf(l1);
                int row = m * 16 + (lane >> 2) + 8;
                *(float2*)&g_E[(long)row * VPAD + c0] = make_float2(e0, e1);
                int slot = m * 2 + 1;
                rsum[slot] += e0 + e1;
                if (l0 > rmax[slot] || (l0 == rmax[slot] && c0 < ridx[slot])) { rmax[slot] = l0; ridx[slot] = c0; }
                if (l1 > rmax[slot] || (l1 == rmax[slot] && c0 + 1 < ridx[slot])) { rmax[slot] = l1; ridx[slot] = c0 + 1; }
            }
        }
    }
    #pragma unroll
    for (int off = 1; off <= 2; off <<= 1) {
        #pragma unroll
        for (int slot = 0; slot < 4; slot++) {
            rsum[slot] += __shfl_xor_sync(0xffffffffu, rsum[slot], off);
            float v = __shfl_xor_sync(0xffffffffu, rmax[slot], off);
            int   i = __shfl_xor_sync(0xffffffffu, ridx[slot], off);
            if (v > rmax[slot] || (v == rmax[slot] && i < ridx[slot])) { rmax[slot] = v; ridx[slot] = i; }
        }
    }
    if ((lane & 3) == 0) {
        #pragma unroll
        for (int slot = 0; slot < 4; slot++) {
            int row = (slot >> 1) * 16 + (lane >> 2) + (slot & 1) * 8;
            s_sum[w][row] = rsum[slot];
            s_max[w][row] = rmax[slot];
            s_idx[w][row] = ridx[slot];
        }
    }
    __syncthreads();
    if (tid < 32) {
        int row = tid;
        float ps = 0.f, pv = -3e38f; int pi = 0;
        #pragma unroll
        for (int ww = 0; ww < 16; ww++) {
            ps += s_sum[ww][row];
            float v = s_max[ww][row]; int i = s_idx[ww][row];
            if (v > pv || (v == pv && i < pi)) { pv = v; pi = i; }
        }
        g_psum[row * NBP + bx] = ps;
        g_pmax[row * NBP + bx] = pv;
        g_pidx[row * NBP + bx] = pi;
    }
}

// ---------------- combine partials: invS + argmax + embed feedback ----------------
__global__ void __launch_bounds__(128) k_comb(const float* __restrict__ emb) {
    __shared__ float rs[128], rv[128];
    __shared__ int   ri[128];
    int row = blockIdx.x, tid = threadIdx.x;
    float s = 0.f, mv = -3e38f; int mi = 0;
    for (int i = tid; i < NBLK; i += 128) {
        s += g_psum[row * NBP + i];
        float v = g_pmax[row * NBP + i]; int ix = g_pidx[row * NBP + i];
        if (v > mv || (v == mv && ix < mi)) { mv = v; mi = ix; }
    }
    rs[tid] = s; rv[tid] = mv; ri[tid] = mi;
    __syncthreads();
    for (int st = 64; st > 0; st >>= 1) {
        if (tid < st) {
            rs[tid] += rs[tid + st];
            float v = rv[tid + st]; int i = ri[tid + st];
            if (v > rv[tid] || (v == rv[tid] && i < ri[tid])) { rv[tid] = v; ri[tid] = i; }
        }
        __syncthreads();
    }
    if (tid == 0) g_invS[row] = 1.0f / rs[0];
    int am = ri[0];
    for (int j = tid; j < 512; j += 128)
        g_xcur[row * 512 + j] = emb[(long)am * 512 + j];
}

// ---------------- final-step y write ----------------
__global__ void k_writey(float* __restrict__ out_y, int t, int T) {
    int b = blockIdx.y;
    float inv = g_invS[b];
    const float* erow = &g_E[(long)b * VPAD];
    float* yrow = &out_y[((long)b * T + t) * VOCAB];
    for (int j = blockIdx.x * blockDim.x + threadIdx.x; j < VOCAB; j += gridDim.x * blockDim.x)
        yrow[j] = erow[j] * inv;
}

// ---------------- host launcher ----------------
extern "C" void kernel_launch(void* const* d_in, const int* in_sizes, int n_in,
                              void* d_out, int out_size) {
    const int*   x      = (const int*)d_in[0];
    const float* h_prev = (const float*)d_in[3];
    const float* emb    = (const float*)d_in[4];
    const float* U0     = (const float*)d_in[5];
    const float* W0     = (const float*)d_in[6];
    const float* b0     = (const float*)d_in[7];
    const float* V0     = (const float*)d_in[8];
    const float* c0     = (const float*)d_in[9];
    const float* U1     = (const float*)d_in[10];
    const float* W1     = (const float*)d_in[11];
    const float* b1     = (const float*)d_in[12];
    const float* V1     = (const float*)d_in[13];
    const float* c1     = (const float*)d_in[14];

    float* out = (float*)d_out;
    int T = out_size / (BB * (HH + VOCAB));
    float* out_h = out;
    float* out_y = out + (long)BB * T * HH;

    float *p_xcur, *p_h0, *p_h1;
    cudaGetSymbolAddress((void**)&p_xcur, g_xcur);
    cudaGetSymbolAddress((void**)&p_h0,   g_h0s);
    cudaGetSymbolAddress((void**)&p_h1,   g_h1s);

    const int SMEM_DUAL   = (16512 * 2 + 2064 * 2 + 256 + 160 + 32) * 4;
    const int SMEM_SINGLE = (16512 + 2064 + 256 + 160 + 32) * 4;
    static bool attr_set = false;
    if (!attr_set) {
        cudaFuncSetAttribute(k_cellx<0>, cudaFuncAttributeMaxDynamicSharedMemorySize, SMEM_DUAL);
        cudaFuncSetAttribute(k_cellx<1>, cudaFuncAttributeMaxDynamicSharedMemorySize, SMEM_SINGLE);
        cudaFuncSetAttribute(k_cellx<2>, cudaFuncAttributeMaxDynamicSharedMemorySize, SMEM_DUAL);
        attr_set = true;
    }

    k_init<<<BB, 512>>>(x, h_prev, emb);
    k_pack_c1<<<(VPAD + 255) / 256, 256>>>(c1);
    k_pack_b<<<dim3(VPAD / 256, 32), 256>>>(V1);

    for (int t = 0; t < T; t++) {
        int cur = t & 1;
        float* h0c = p_h0 + cur * BB * HH;
        float* h0n = p_h0 + (cur ^ 1) * BB * HH;
        float* h1c = p_h1 + cur * BB * HH;
        float* h1n = p_h1 + (cur ^ 1) * BB * HH;

        // h0 = tanh(x@U0 + h0p@W0 + b0)   (+ y(t-1) first half)
        k_cellx<0><<<128, 256, SMEM_DUAL>>>(p_xcur, h0c, U0, W0, b0, h0n,
                                            nullptr, out_y, t, t - 1, T);
        // e0 = exp(h0@V0 + c0) + partials (+ y(t-1) second half)
        k_cellx<1><<<128, 256, SMEM_SINGLE>>>(h0n, nullptr, V0, nullptr, c0, nullptr,
                                              nullptr, out_y, t, t - 1, T);
        // h1 = tanh(x1@U1 + h1p@W1 + b1) with x1 computed inline; out_h + frag pack
        k_cellx<2><<<128, 256, SMEM_DUAL>>>(nullptr, h1c, U1, W1, b1, h1n,
                                            out_h, nullptr, t, -1, T);
        // logits1 -> exp + partials
        k_big<<<NBLK, 512>>>();
        // invS + argmax + feedback embed
        k_comb<<<BB, 128>>>(emb);
    }
    // final step's y
    k_writey<<<dim3(64, BB), 256>>>(out_y, T - 1, T);
}